// round 4
// baseline (speedup 1.0000x reference)
#include <cuda_runtime.h>

typedef unsigned long long ull;

#define Bn 16
#define Cn 32
#define Fn 32
#define Tn 2048
#define Kn 129
#define TILE 1024
#define NTHREADS 64

// packed f32x2 fma: d = a*b + d  (two independent fp32 FMAs per instruction)
__device__ __forceinline__ void fma2(ull& d, ull a, ull b) {
    asm("fma.rn.f32x2 %0, %1, %2, %0;" : "+l"(d) : "l"(a), "l"(b));
}

__global__ __launch_bounds__(NTHREADS)
void wavelet_synth_kernel(
    const float* __restrict__ coeffs,     // (B,2,F,7,5,T)
    const int*   __restrict__ rows,       // (C)
    const int*   __restrict__ cols,       // (C)
    const float* __restrict__ ri_scale,   // (F)
    const float* __restrict__ ri_shift,   // (F)
    const float* __restrict__ freq_gain,  // (F)
    const float* __restrict__ synth_w,    // (C*2F, 1, K)
    float*       __restrict__ out)        // (B,C,T)
{
    // psm: skewed pair array. logical slot l in [0, TILE+128) holds (z[l], z[l+1])
    // (z index = local, z[l] corresponds to time T0 - 65 + l + ... see fill).
    // skewed ull index q(l) = l + (l>>4). max q = 1151 + 71 = 1222.
    __shared__ ull psm[1232];
    __shared__ ull wsm[65];   // wsm[u] = (w[2u+1], w[2u]) for u<64; wsm[64] = (0, w[128])

    const int tid  = threadIdx.x;
    const int half = blockIdx.x & 1;
    const int bc   = blockIdx.x >> 1;
    const int b    = bc >> 5;          // / C
    const int c    = bc & 31;          // % C
    const int T0   = half << 10;       // 0 or 1024

    const int rr = rows[c];
    const int cc = cols[c];

    ull acc[16];
#pragma unroll
    for (int r = 0; r < 16; ++r) acc[r] = 0ull;

    float*  pf = reinterpret_cast<float*>(psm);
    float2* wf = reinterpret_cast<float2*>(wsm);

    for (int i = 0; i < 64; ++i) {
        const int   f   = i & 31;
        const int   ri  = i >> 5;
        const float g   = freq_gain[f];
        const float a   = g / (ri_scale[f] + 1e-12f);
        const float bsh = ri_shift[f] * g;
        const float* src = coeffs +
            (size_t)((((b * 2 + ri) * Fn + f) * 7 + rr) * 5 + cc) * Tn;

        // ---- fill z (TILE+129 values), storing each value into p[lz].x and p[lz-1].y
        for (int lz = tid; lz < TILE + 129; lz += NTHREADS) {
            const int t = T0 + lz - 65;   // time index of z value lz
            float v = 0.f;
            if ((unsigned)t < (unsigned)Tn) v = fmaf(src[t], a, -bsh);
            if (lz < TILE + 128) pf[2 * (lz + (lz >> 4))] = v;
            if (lz > 0) { const int lm = lz - 1; pf[2 * (lm + (lm >> 4)) + 1] = v; }
        }
        // ---- fill swapped weight pairs
        const float* wc = synth_w + (size_t)(c * 64 + i) * Kn;
        for (int u = tid; u < 65; u += NTHREADS) {
            float2 wv;
            if (u < 64) { wv.x = wc[2 * u + 1]; wv.y = wc[2 * u]; }
            else        { wv.x = 0.f;           wv.y = wc[128];   }
            wf[u] = wv;
        }
        __syncthreads();

        // ---- compute: outputs t = T0 + 16*tid + r, r = 0..15
        // pair slot needed at step u for output r:  l = 16*tid + r + 128 - 2u
        // skewed address with c = l - 16*tid:  q = 17*tid + c + (c>>4)
        const ull* pb = psm + 17 * tid;
        ull ring[18];                       // ring slot s = (l - 16*tid - 128) mod 18
#pragma unroll
        for (int r = 0; r < 16; ++r) ring[r] = pb[136 + r];   // c = 128+r -> idx 136+r

#pragma unroll 1
        for (int ub = 0; ub < 63; ub += 9) {   // ub multiple of 9 -> 2*ub ≡ 0 (mod 18)
#pragma unroll
            for (int du = 0; du < 9; ++du) {
                const int u  = ub + du;
                const ull wv = wsm[u];
#pragma unroll
                for (int r = 0; r < 16; ++r) {
                    const int s = (((r - 2 * du) % 18) + 18) % 18;
                    fma2(acc[r], ring[s], wv);
                }
                // prefetch the two pair slots for step u+1
                const int c0 = 126 - 2 * u;
                const int s0 = (((-2 * du - 2) % 18) + 18) % 18;
                const int s1 = (((-2 * du - 1) % 18) + 18) % 18;
                ring[s0] = pb[c0 + (c0 >> 4)];
                ring[s1] = pb[(c0 + 1) + ((c0 + 1) >> 4)];
            }
        }
        {   // u = 63  (2*63 ≡ 0 mod 18 -> s = r)
            const ull wv = wsm[63];
#pragma unroll
            for (int r = 0; r < 16; ++r) fma2(acc[r], ring[r], wv);
            ring[16] = pb[0];   // c = 0 -> rel -128 -> slot 16
            ring[17] = pb[1];   // c = 1 -> rel -127 -> slot 17
        }
        {   // u = 64  (final even tap j=128 via wsm[64] = (0, w[128]))
            const ull wv = wsm[64];
#pragma unroll
            for (int r = 0; r < 16; ++r) {
                const int s = (r + 16) % 18;
                fma2(acc[r], ring[s], wv);
            }
        }
        __syncthreads();
    }

    // out[b, c, T0 + 16*tid + r] = odd-tap half + even-tap half
    const int obase = (b * Cn + c) * Tn + T0 + tid * 16;
#pragma unroll
    for (int r = 0; r < 16; ++r) {
        const float lo = __int_as_float((int)(acc[r] & 0xffffffffull));
        const float hi = __int_as_float((int)(acc[r] >> 32));
        out[obase + r] = lo + hi;
    }
}

extern "C" void kernel_launch(void* const* d_in, const int* in_sizes, int n_in,
                              void* d_out, int out_size) {
    (void)in_sizes; (void)n_in; (void)out_size;
    const float* coeffs    = (const float*)d_in[0];
    const int*   rows      = (const int*)  d_in[1];
    const int*   cols      = (const int*)  d_in[2];
    const float* ri_scale  = (const float*)d_in[3];
    const float* ri_shift  = (const float*)d_in[4];
    const float* freq_gain = (const float*)d_in[5];
    const float* synth_w   = (const float*)d_in[6];
    float* out = (float*)d_out;

    wavelet_synth_kernel<<<Bn * Cn * 2, NTHREADS>>>(
        coeffs, rows, cols, ri_scale, ri_shift, freq_gain, synth_w, out);
}

// round 6
// speedup vs baseline: 1.3995x; 1.3995x over previous
#include <cuda_runtime.h>

typedef unsigned long long ull;

#define Bn 16
#define Cn 32
#define Fn 32
#define Tn 2048
#define Kn 129
#define TILE 1024
#define NTHREADS 64
#define NZ 19          // z values per thread: 64*19 = 1216 >= TILE+129 = 1153

// packed f32x2 fma: d = a*b + d  (two independent fp32 FMAs per instruction)
__device__ __forceinline__ void fma2(ull& d, ull a, ull b) {
    asm("fma.rn.f32x2 %0, %1, %2, %0;" : "+l"(d) : "l"(a), "l"(b));
}

__global__ __launch_bounds__(NTHREADS, 7)
void wavelet_synth_kernel(
    const float* __restrict__ coeffs,     // (B,2,F,7,5,T)
    const int*   __restrict__ rows,       // (C)
    const int*   __restrict__ cols,       // (C)
    const float* __restrict__ ri_scale,   // (F)
    const float* __restrict__ ri_shift,   // (F)
    const float* __restrict__ freq_gain,  // (F)
    const float* __restrict__ synth_w,    // (C*2F, 1, K)
    float*       __restrict__ out)        // (B,C,T)
{
    // psm: skewed pair array. logical slot l in [0, TILE+128) holds (z[l], z[l+1]).
    // skewed ull index q(l) = l + (l>>4).
    __shared__ ull psm[1232];
    __shared__ ull wsm[66];   // wsm[u] = (w[2u+1], w[2u]) u<64; wsm[64] = (0, w[128])

    const int tid  = threadIdx.x;
    const int half = blockIdx.x & 1;
    const int bc   = blockIdx.x >> 1;
    const int b    = bc >> 5;          // / C
    const int c    = bc & 31;          // % C
    const int T0   = half << 10;       // 0 or 1024

    const int rr = rows[c];
    const int cc = cols[c];

    ull acc[16];
#pragma unroll
    for (int r = 0; r < 16; ++r) acc[r] = 0ull;

    float*  pf = reinterpret_cast<float*>(psm);
    float2* wf = reinterpret_cast<float2*>(wsm);

    // ---------------- prefetch registers (raw loads only; no dependent math) ----
    float zreg[NZ];
    float w0, w1, w2;

    // prologue: prefetch i = 0 (ri=0, f=0)
    {
        const float* src = coeffs + (size_t)(((b * 2 * Fn) * 7 + rr) * 5 + cc) * Tn;
#pragma unroll
        for (int k = 0; k < NZ; ++k) {
            const int lz = tid + (k << 6);
            const int t  = T0 + lz - 65;
            zreg[k] = (lz < TILE + 129 && (unsigned)t < (unsigned)Tn) ? src[t] : 0.f;
        }
        const float* wc = synth_w + (size_t)(c * 64) * Kn;
        w0 = wc[2 * tid + 1];
        w1 = wc[2 * tid];
        w2 = (tid == 0) ? wc[128] : 0.f;
    }

    for (int i = 0; i < 64; ++i) {
        const int   f   = i & 31;
        const float g   = freq_gain[f];
        const float a   = g / (ri_scale[f] + 1e-12f);
        const float bsh = ri_shift[f] * g;

        if (i) __syncthreads();   // prev compute done before overwriting psm/wsm

        // ---- store prefetched z -> skewed pair array (with transform)
        // IMPORTANT: padded positions (t outside [0,Tn)) must store exactly 0,
        // not fmaf(0,a,-bsh) = -bsh. Predicate on t validity here.
#pragma unroll
        for (int k = 0; k < NZ; ++k) {
            const int lz = tid + (k << 6);
            if (lz < TILE + 129) {
                const int t = T0 + lz - 65;
                const float v = ((unsigned)t < (unsigned)Tn)
                                    ? fmaf(zreg[k], a, -bsh) : 0.f;
                if (lz < TILE + 128) pf[2 * (lz + (lz >> 4))] = v;
                if (lz > 0) { const int lm = lz - 1; pf[2 * (lm + (lm >> 4)) + 1] = v; }
            }
        }
        // ---- store prefetched (swapped) weight pairs
        wf[tid] = make_float2(w0, w1);
        if (tid == 0) wf[64] = make_float2(0.f, w2);
        __syncthreads();

        // ---- issue prefetch for i+1 (raw loads; complete under the compute below)
        if (i < 63) {
            const int in  = i + 1;
            const int fn  = in & 31;
            const int rin = in >> 5;
            const float* src = coeffs +
                (size_t)((((b * 2 + rin) * Fn + fn) * 7 + rr) * 5 + cc) * Tn;
#pragma unroll
            for (int k = 0; k < NZ; ++k) {
                const int lz = tid + (k << 6);
                const int t  = T0 + lz - 65;
                zreg[k] = (lz < TILE + 129 && (unsigned)t < (unsigned)Tn) ? src[t] : 0.f;
            }
            const float* wc = synth_w + (size_t)(c * 64 + in) * Kn;
            w0 = wc[2 * tid + 1];
            w1 = wc[2 * tid];
            if (tid == 0) w2 = wc[128];
        }

        // ---- compute: outputs t = T0 + 16*tid + r, r = 0..15
        // pair slot needed at step u for output r:  l = 16*tid + r + 128 - 2u
        // skewed address with cl = l - 16*tid:  q = 17*tid + cl + (cl>>4)
        const ull* pb = psm + 17 * tid;
        ull ring[18];                     // ring slot s = (l - 16*tid - 128) mod 18
#pragma unroll
        for (int r = 0; r < 16; ++r) ring[r] = pb[136 + r];   // cl = 128+r

        ull wv = wsm[0];
        const ull* wp = wsm;
#pragma unroll 1
        for (int ub = 0; ub < 63; ub += 9) {   // ub multiple of 9 -> 2*ub ≡ 0 (mod 18)
            const int base = 126 - 2 * ub;
#pragma unroll
            for (int du = 0; du < 9; ++du) {
                const ull wnext = wp[du + 1];
#pragma unroll
                for (int r = 0; r < 16; ++r) {
                    const int s = (((r - 2 * du) % 18) + 18) % 18;
                    fma2(acc[r], ring[s], wv);
                }
                // prefetch the two pair slots for step u+1
                const int c0 = base - 2 * du;          // = 126 - 2u
                const int s0 = (((-2 * du - 2) % 18) + 18) % 18;
                const int s1 = (((-2 * du - 1) % 18) + 18) % 18;
                ring[s0] = pb[c0 + (c0 >> 4)];
                ring[s1] = pb[(c0 + 1) + ((c0 + 1) >> 4)];
                wv = wnext;
            }
            wp += 9;
        }
        {   // u = 63  (2*63 ≡ 0 mod 18 -> s = r); wv == wsm[63] from the pipeline
#pragma unroll
            for (int r = 0; r < 16; ++r) fma2(acc[r], ring[r], wv);
            ring[16] = pb[0];   // cl = 0 -> slot 16
            ring[17] = pb[1];   // cl = 1 -> slot 17
            wv = wsm[64];
        }
        {   // u = 64  (final even tap j=128 via (0, w[128]))
#pragma unroll
            for (int r = 0; r < 16; ++r) {
                const int s = (r + 16) % 18;
                fma2(acc[r], ring[s], wv);
            }
        }
    }

    // out[b, c, T0 + 16*tid + r] = odd-tap half + even-tap half
    const int obase = (b * Cn + c) * Tn + T0 + tid * 16;
#pragma unroll
    for (int r = 0; r < 16; ++r) {
        const float lo = __int_as_float((int)(acc[r] & 0xffffffffull));
        const float hi = __int_as_float((int)(acc[r] >> 32));
        out[obase + r] = lo + hi;
    }
}

extern "C" void kernel_launch(void* const* d_in, const int* in_sizes, int n_in,
                              void* d_out, int out_size) {
    (void)in_sizes; (void)n_in; (void)out_size;
    const float* coeffs    = (const float*)d_in[0];
    const int*   rows      = (const int*)  d_in[1];
    const int*   cols      = (const int*)  d_in[2];
    const float* ri_scale  = (const float*)d_in[3];
    const float* ri_shift  = (const float*)d_in[4];
    const float* freq_gain = (const float*)d_in[5];
    const float* synth_w   = (const float*)d_in[6];
    float* out = (float*)d_out;

    wavelet_synth_kernel<<<Bn * Cn * 2, NTHREADS>>>(
        coeffs, rows, cols, ri_scale, ri_shift, freq_gain, synth_w, out);
}